// round 15
// baseline (speedup 1.0000x reference)
#include <cuda_runtime.h>
#include <cuda_fp16.h>
#include <cstdint>

#define NN 4096
#define DD 512
#define BM 256                   // CTA tile rows
#define BN 128                   // CTA tile cols
#define KC 64                    // fp16 K elems per chunk = 128B per row
#define NCHUNK (DD / KC)         // 8
#define MARGIN_F 0.3f

#define A_BYTES (BM * 128)       // 32 KB per stage
#define B_BYTES (BN * 128)       // 16 KB per stage
#define STAGE_BYTES (A_BYTES + B_BYTES)
#define A_OFF(s) ((s) * STAGE_BYTES)
#define B_OFF(s) ((s) * STAGE_BYTES + A_BYTES)
#define DYN_SMEM (2 * STAGE_BYTES)   // 96 KB

__device__ float    g_e1[NN];
__device__ float    g_e2[NN];
__device__ unsigned g_ap[NN];      // non-negative float bits, atomicMax
__device__ unsigned g_an[NN];      // non-negative float bits, atomicMin
__device__ int      g_lab[NN];
__device__ __half   g_srch[NN * DD];   // fp16 copies (4 MB each)
__device__ __half   g_tgth[NN * DD];

// ---------------------------------------------------------------------------
__device__ __forceinline__ uint32_t h2_bits(__half2 h) {
    return *reinterpret_cast<uint32_t*>(&h);
}
__device__ __forceinline__ uint32_t smem_u32(const void* p) {
    uint32_t a;
    asm("{ .reg .u64 t; cvta.to.shared.u64 t, %1; cvt.u32.u64 %0, t; }"
        : "=r"(a) : "l"(p));
    return a;
}
__device__ __forceinline__ void cp_async16(uint32_t dst, const void* src) {
    asm volatile("cp.async.cg.shared.global [%0], [%1], 16;" :: "r"(dst), "l"(src));
}
__device__ __forceinline__ void ldsm_x4(uint32_t addr, uint32_t& r0, uint32_t& r1,
                                        uint32_t& r2, uint32_t& r3) {
    asm volatile("ldmatrix.sync.aligned.m8n8.x4.shared.b16 {%0,%1,%2,%3}, [%4];"
                 : "=r"(r0), "=r"(r1), "=r"(r2), "=r"(r3) : "r"(addr));
}
__device__ __forceinline__ void mma_f16(float* d, uint32_t a0, uint32_t a1,
                                        uint32_t a2, uint32_t a3,
                                        uint32_t b0, uint32_t b1) {
    asm volatile(
        "mma.sync.aligned.m16n8k16.row.col.f32.f16.f16.f32 "
        "{%0,%1,%2,%3}, {%4,%5,%6,%7}, {%8,%9}, {%0,%1,%2,%3};"
        : "+f"(d[0]), "+f"(d[1]), "+f"(d[2]), "+f"(d[3])
        : "r"(a0), "r"(a1), "r"(a2), "r"(a3), "r"(b0), "r"(b1));
}

// ---------------------------------------------------------------------------
// prep: warp-per-(row, array) fp32->fp16 convert + norms + accumulator init.
// Block 0 additionally: label dtype detect + normalize.
// ---------------------------------------------------------------------------
__global__ void __launch_bounds__(256) prep_kernel(const float* __restrict__ src,
                                                   const float* __restrict__ tgt,
                                                   const int* __restrict__ lab32) {
    const int wid = threadIdx.x >> 5;
    const int lid = threadIdx.x & 31;
    const int slot = blockIdx.x * 8 + wid;
    const int row = slot >> 1;
    const int arr = slot & 1;

    const float* base = arr ? tgt : src;
    __half* dsth = arr ? g_tgth : g_srch;

    const float4* s4 = (const float4*)(base + (size_t)row * DD);
    uint2* oh = (uint2*)(dsth + (size_t)row * DD);

    float4 xs[4];
#pragma unroll
    for (int i = 0; i < 4; i++) xs[i] = s4[lid + 32 * i];

    float a = 0.f;
#pragma unroll
    for (int i = 0; i < 4; i++) {
        float4 x = xs[i];
        a = fmaf(x.x, x.x, a); a = fmaf(x.y, x.y, a);
        a = fmaf(x.z, x.z, a); a = fmaf(x.w, x.w, a);
        uint2 o;
        o.x = h2_bits(__floats2half2_rn(x.x, x.y));
        o.y = h2_bits(__floats2half2_rn(x.z, x.w));
        __stcg(&oh[lid + 32 * i], o);
    }
#pragma unroll
    for (int o = 16; o > 0; o >>= 1)
        a += __shfl_xor_sync(0xffffffffu, a, o);
    if (lid == 0) {
        if (arr == 0) {
            g_e1[row] = a;
            g_ap[row] = 0u;
            g_an[row] = 0x7f800000u;
        } else {
            g_e2[row] = a;
        }
    }

    if (blockIdx.x == 0) {
        __shared__ int any_odd_nonzero;
        const int t = threadIdx.x;
        if (t == 0) any_odd_nonzero = 0;
        __syncthreads();
        int local = 0;
        for (int i = 2 * t + 1; i < NN; i += 2 * 256)
            if (lab32[i] != 0) local = 1;
        if (local) atomicOr(&any_odd_nonzero, 1);
        __syncthreads();
        bool is64 = (any_odd_nonzero == 0);
        for (int i = t; i < NN; i += 256)
            g_lab[i] = is64 ? lab32[2 * i] : lab32[i];
    }
}

// ---------------------------------------------------------------------------
// dist_mma: 256x128 CTA tile, 8 warps 4(M)x2(N), warp tile 64x64.
// Same pipeline skeleton as best measured (fill next chunk, commit, wait 1,
// sync, compute, sync). wf/MMA = 1.0 (vs 1.5 at 32x64 warp tile).
// ---------------------------------------------------------------------------
__global__ void __launch_bounds__(256, 1) dist_mma_kernel() {
    extern __shared__ char smem[];
    __shared__ float sE1[BM], sE2[BN];
    __shared__ int   sLr[BM], sLc[BN];
    __shared__ unsigned sAp[BM], sAn[BM];

    const int tid = threadIdx.x;
    const int wid = tid >> 5;
    const int lid = tid & 31;
    const int gid = lid >> 2;
    const int t4  = lid & 3;
    const int warpM = wid & 3;    // 0..3 -> 64-row slab
    const int warpN = wid >> 2;   // 0..1 -> 64-col slab
    const int rowBase = blockIdx.y * BM;
    const int colBase = blockIdx.x * BN;

    // per-tile metadata (256 rows, 128 cols)
    sAp[tid] = 0u;
    sAn[tid] = 0x7f800000u;
    sE1[tid] = g_e1[rowBase + tid];
    sLr[tid] = g_lab[rowBase + tid];
    if (tid < BN) {
        sE2[tid] = g_e2[colBase + tid];
        sLc[tid] = g_lab[colBase + tid];
    }

    const uint32_t sbase = smem_u32(smem);
    const int l7 = lid & 7;
    // A: mf 0..3: row = warpM*64 + mf*16 + ((lid>>3)&1)*8 + l7 ; c16 += lid>>4
    uint32_t aRow[4];
#pragma unroll
    for (int mf = 0; mf < 4; mf++)
        aRow[mf] = (uint32_t)((warpM * 64 + mf * 16 + ((lid >> 3) & 1) * 8 + l7) * 128);
    const int aSel = lid >> 4;
    // B: p 0..3: col = warpN*64 + p*16 + (lid>>4)*8 + l7 ; c16 += (lid>>3)&1
    uint32_t bCol[4];
#pragma unroll
    for (int p = 0; p < 4; p++)
        bCol[p] = (uint32_t)((warpN * 64 + p * 16 + (lid >> 4) * 8 + l7) * 128);
    const int bSel = (lid >> 3) & 1;

    // chunk loader: A 256 rows + B 128 rows x 128B, SW128 swizzle
    auto load_chunk = [&](int rb, int cb, int kt, uint32_t dstA, uint32_t dstB) {
#pragma unroll
        for (int i = 0; i < 8; i++) {
            int f = tid + i * 256;        // 0..2047 16B slots
            int r = f >> 3;
            int c16 = f & 7;
            const __half* g = g_srch + (size_t)(rb + r) * DD + kt + c16 * 8;
            cp_async16(dstA + r * 128 + ((c16 ^ (r & 7)) << 4), g);
        }
#pragma unroll
        for (int i = 0; i < 4; i++) {
            int f = tid + i * 256;        // 0..1023
            int r = f >> 3;
            int c16 = f & 7;
            const __half* g = g_tgth + (size_t)(cb + r) * DD + kt + c16 * 8;
            cp_async16(dstB + r * 128 + ((c16 ^ (r & 7)) << 4), g);
        }
    };

    float acc[4][8][4];
#pragma unroll
    for (int mf = 0; mf < 4; mf++)
#pragma unroll
        for (int nf = 0; nf < 8; nf++)
#pragma unroll
            for (int v = 0; v < 4; v++) acc[mf][nf][v] = 0.f;

    load_chunk(rowBase, colBase, 0, sbase + A_OFF(0), sbase + B_OFF(0));
    asm volatile("cp.async.commit_group;");

    for (int c = 0; c < NCHUNK; c++) {
        int st = c & 1;
        if (c + 1 < NCHUNK) {
            int sn = (c + 1) & 1;
            load_chunk(rowBase, colBase, (c + 1) * KC,
                       sbase + A_OFF(sn), sbase + B_OFF(sn));
            asm volatile("cp.async.commit_group;");
            asm volatile("cp.async.wait_group 1;");
        } else {
            asm volatile("cp.async.wait_group 0;");
        }
        __syncthreads();

        const uint32_t Ab = sbase + A_OFF(st);
        const uint32_t Bb = sbase + B_OFF(st);
#pragma unroll
        for (int s = 0; s < 4; s++) {          // 4 x K=16
            uint32_t a[4][4];
#pragma unroll
            for (int mf = 0; mf < 4; mf++) {
                uint32_t addr = Ab + aRow[mf] + ((uint32_t)((s * 2 + aSel) ^ l7) << 4);
                ldsm_x4(addr, a[mf][0], a[mf][1], a[mf][2], a[mf][3]);
            }
#pragma unroll
            for (int p = 0; p < 4; p++) {
                uint32_t b0a, b1a, b0b, b1b;
                uint32_t addr = Bb + bCol[p] + ((uint32_t)((s * 2 + bSel) ^ l7) << 4);
                ldsm_x4(addr, b0a, b1a, b0b, b1b);
#pragma unroll
                for (int mf = 0; mf < 4; mf++) {
                    mma_f16(acc[mf][2 * p],     a[mf][0], a[mf][1], a[mf][2], a[mf][3], b0a, b1a);
                    mma_f16(acc[mf][2 * p + 1], a[mf][0], a[mf][1], a[mf][2], a[mf][3], b0b, b1b);
                }
            }
        }
        __syncthreads();
    }

    // ---- epilogue: dist -> clamp -> mask -> row max/min ----
#pragma unroll
    for (int mf = 0; mf < 4; mf++) {
#pragma unroll
        for (int half = 0; half < 2; half++) {
            int row = warpM * 64 + mf * 16 + half * 8 + gid;
            float e1v = sE1[row];
            int   lr  = sLr[row];
            float apv = 0.f;
            float anv = __int_as_float(0x7f800000);
#pragma unroll
            for (int nf = 0; nf < 8; nf++) {
                int c0 = warpN * 64 + nf * 8 + t4 * 2;
#pragma unroll
                for (int v = 0; v < 2; v++) {
                    int col = c0 + v;
                    float d = fmaf(-2.f, acc[mf][nf][half * 2 + v], e1v + sE2[col]);
                    d = fmaxf(d, 0.f);
                    if (lr == sLc[col]) apv = fmaxf(apv, d);
                    else                anv = fminf(anv, d);
                }
            }
#pragma unroll
            for (int o = 1; o <= 2; o <<= 1) {
                apv = fmaxf(apv, __shfl_xor_sync(0xffffffffu, apv, o));
                anv = fminf(anv, __shfl_xor_sync(0xffffffffu, anv, o));
            }
            if (t4 == 0) {
                atomicMax(&sAp[row], __float_as_uint(apv));
                atomicMin(&sAn[row], __float_as_uint(anv));
            }
        }
    }
    __syncthreads();
    atomicMax(&g_ap[rowBase + tid], sAp[tid]);
    atomicMin(&g_an[rowBase + tid], sAn[tid]);
}

// ---------------------------------------------------------------------------
// reduce: deterministic single-block mean; 512 threads, 8 rows/thread
// ---------------------------------------------------------------------------
__global__ void __launch_bounds__(512) reduce_kernel(float* __restrict__ out) {
    __shared__ float sw[16];
    int t = threadIdx.x;  // 512; thread t owns rows 8t..8t+7
    uint4 ap0 = *(const uint4*)&g_ap[t * 8];
    uint4 an0 = *(const uint4*)&g_an[t * 8];
    uint4 ap1 = *(const uint4*)&g_ap[t * 8 + 4];
    uint4 an1 = *(const uint4*)&g_an[t * 8 + 4];
    float s = fmaxf(__uint_as_float(ap0.x) - __uint_as_float(an0.x) + MARGIN_F, 0.f)
            + fmaxf(__uint_as_float(ap0.y) - __uint_as_float(an0.y) + MARGIN_F, 0.f)
            + fmaxf(__uint_as_float(ap0.z) - __uint_as_float(an0.z) + MARGIN_F, 0.f)
            + fmaxf(__uint_as_float(ap0.w) - __uint_as_float(an0.w) + MARGIN_F, 0.f)
            + fmaxf(__uint_as_float(ap1.x) - __uint_as_float(an1.x) + MARGIN_F, 0.f)
            + fmaxf(__uint_as_float(ap1.y) - __uint_as_float(an1.y) + MARGIN_F, 0.f)
            + fmaxf(__uint_as_float(ap1.z) - __uint_as_float(an1.z) + MARGIN_F, 0.f)
            + fmaxf(__uint_as_float(ap1.w) - __uint_as_float(an1.w) + MARGIN_F, 0.f);
#pragma unroll
    for (int o = 16; o > 0; o >>= 1) s += __shfl_xor_sync(0xffffffffu, s, o);
    if ((t & 31) == 0) sw[t >> 5] = s;
    __syncthreads();
    if (t < 16) {
        float v = sw[t];
#pragma unroll
        for (int o = 8; o > 0; o >>= 1) v += __shfl_xor_sync(0xffffu, v, o);
        if (t == 0) out[0] = v * (1.0f / (float)NN);
    }
}

// ---------------------------------------------------------------------------
extern "C" void kernel_launch(void* const* d_in, const int* in_sizes, int n_in,
                              void* d_out, int out_size) {
    const float* src = (const float*)d_in[0];
    const float* tgt = (const float*)d_in[1];
    const int*   lab = (const int*)d_in[2];

    cudaFuncSetAttribute(dist_mma_kernel,
                         cudaFuncAttributeMaxDynamicSharedMemorySize, DYN_SMEM);

    prep_kernel<<<NN / 4, 256>>>(src, tgt, lab);
    dist_mma_kernel<<<dim3(NN / BN, NN / BM), 256, DYN_SMEM>>>();
    reduce_kernel<<<1, 512>>>((float*)d_out);
}

// round 16
// speedup vs baseline: 1.2250x; 1.2250x over previous
#include <cuda_runtime.h>
#include <cuda_fp16.h>
#include <cstdint>

#define NN 4096
#define DD 512
#define BM 128
#define BN 128
#define KC 64                    // fp16 K elems per chunk = 128B per row
#define NCHUNK (DD / KC)         // 8
#define MARGIN_F 0.3f

#define TILE_BYTES (BM * 128)    // 16 KB per operand per stage
#define A_OFF(s) ((s) * TILE_BYTES)
#define B_OFF(s) (2 * TILE_BYTES + (s) * TILE_BYTES)
#define DYN_SMEM (4 * TILE_BYTES)   // 64 KB (2-stage double buffer)

__device__ float    g_e1[NN];
__device__ float    g_e2[NN];
__device__ unsigned g_ap[NN];      // non-negative float bits, atomicMax
__device__ unsigned g_an[NN];      // non-negative float bits, atomicMin
__device__ int      g_lab[NN];
__device__ __half   g_srch[NN * DD];   // fp16 copies (4 MB each)
__device__ __half   g_tgth[NN * DD];

// ---------------------------------------------------------------------------
__device__ __forceinline__ uint32_t h2_bits(__half2 h) {
    return *reinterpret_cast<uint32_t*>(&h);
}
__device__ __forceinline__ uint32_t smem_u32(const void* p) {
    uint32_t a;
    asm("{ .reg .u64 t; cvta.to.shared.u64 t, %1; cvt.u32.u64 %0, t; }"
        : "=r"(a) : "l"(p));
    return a;
}
__device__ __forceinline__ void cp_async16(uint32_t dst, const void* src) {
    asm volatile("cp.async.cg.shared.global [%0], [%1], 16;" :: "r"(dst), "l"(src));
}
__device__ __forceinline__ void ldsm_x4(uint32_t addr, uint32_t& r0, uint32_t& r1,
                                        uint32_t& r2, uint32_t& r3) {
    asm volatile("ldmatrix.sync.aligned.m8n8.x4.shared.b16 {%0,%1,%2,%3}, [%4];"
                 : "=r"(r0), "=r"(r1), "=r"(r2), "=r"(r3) : "r"(addr));
}
__device__ __forceinline__ void mma_f16(float* d, uint32_t a0, uint32_t a1,
                                        uint32_t a2, uint32_t a3,
                                        uint32_t b0, uint32_t b1) {
    asm volatile(
        "mma.sync.aligned.m16n8k16.row.col.f32.f16.f16.f32 "
        "{%0,%1,%2,%3}, {%4,%5,%6,%7}, {%8,%9}, {%0,%1,%2,%3};"
        : "+f"(d[0]), "+f"(d[1]), "+f"(d[2]), "+f"(d[3])
        : "r"(a0), "r"(a1), "r"(a2), "r"(a3), "r"(b0), "r"(b1));
}

// ---------------------------------------------------------------------------
// prep: warp-per-(row, array) fp32->fp16 convert + norms + accumulator init.
// Block 0 additionally: label dtype detect + normalize.
// ---------------------------------------------------------------------------
__global__ void __launch_bounds__(256) prep_kernel(const float* __restrict__ src,
                                                   const float* __restrict__ tgt,
                                                   const int* __restrict__ lab32) {
    const int wid = threadIdx.x >> 5;
    const int lid = threadIdx.x & 31;
    const int slot = blockIdx.x * 8 + wid;
    const int row = slot >> 1;
    const int arr = slot & 1;

    const float* base = arr ? tgt : src;
    __half* dsth = arr ? g_tgth : g_srch;

    const float4* s4 = (const float4*)(base + (size_t)row * DD);
    uint2* oh = (uint2*)(dsth + (size_t)row * DD);

    float4 xs[4];
#pragma unroll
    for (int i = 0; i < 4; i++) xs[i] = s4[lid + 32 * i];

    float a = 0.f;
#pragma unroll
    for (int i = 0; i < 4; i++) {
        float4 x = xs[i];
        a = fmaf(x.x, x.x, a); a = fmaf(x.y, x.y, a);
        a = fmaf(x.z, x.z, a); a = fmaf(x.w, x.w, a);
        uint2 o;
        o.x = h2_bits(__floats2half2_rn(x.x, x.y));
        o.y = h2_bits(__floats2half2_rn(x.z, x.w));
        __stcg(&oh[lid + 32 * i], o);
    }
#pragma unroll
    for (int o = 16; o > 0; o >>= 1)
        a += __shfl_xor_sync(0xffffffffu, a, o);
    if (lid == 0) {
        if (arr == 0) {
            g_e1[row] = a;
            g_ap[row] = 0u;
            g_an[row] = 0x7f800000u;
        } else {
            g_e2[row] = a;
        }
    }

    if (blockIdx.x == 0) {
        __shared__ int any_odd_nonzero;
        const int t = threadIdx.x;
        if (t == 0) any_odd_nonzero = 0;
        __syncthreads();
        int local = 0;
        for (int i = 2 * t + 1; i < NN; i += 2 * 256)
            if (lab32[i] != 0) local = 1;
        if (local) atomicOr(&any_odd_nonzero, 1);
        __syncthreads();
        bool is64 = (any_odd_nonzero == 0);
        for (int i = t; i < NN; i += 256)
            g_lab[i] = is64 ? lab32[2 * i] : lab32[i];
    }
}

// ---------------------------------------------------------------------------
// dist_mma: 128x128 CTA tile, 128 threads, 4 warps in 2(M)x2(N), warp tile
// 64x64 (wf/MMA = 1.0), occupancy 2. Pipeline skeleton identical to the
// R7 champion: fill next, commit, wait 1, sync, compute, sync.
// ---------------------------------------------------------------------------
__global__ void __launch_bounds__(128, 2) dist_mma_kernel() {
    extern __shared__ char smem[];
    __shared__ float sE1[BM], sE2[BN];
    __shared__ int   sLr[BM], sLc[BN];
    __shared__ unsigned sAp[BM], sAn[BM];

    const int tid = threadIdx.x;
    const int wid = tid >> 5;
    const int lid = tid & 31;
    const int gid = lid >> 2;
    const int t4  = lid & 3;
    const int warpM = wid & 1;    // 0..1 -> 64-row slab
    const int warpN = wid >> 1;   // 0..1 -> 64-col slab
    const int rowBase = blockIdx.y * BM;
    const int colBase = blockIdx.x * BN;

    // per-tile metadata (128 rows, 128 cols; 128 threads)
    sAp[tid] = 0u;
    sAn[tid] = 0x7f800000u;
    sE1[tid] = g_e1[rowBase + tid];
    sE2[tid] = g_e2[colBase + tid];
    sLr[tid] = g_lab[rowBase + tid];
    sLc[tid] = g_lab[colBase + tid];

    const uint32_t sbase = smem_u32(smem);
    const int l7 = lid & 7;
    // A: mf 0..3: row = warpM*64 + mf*16 + ((lid>>3)&1)*8 + l7 ; c16 += lid>>4
    uint32_t aRow[4];
#pragma unroll
    for (int mf = 0; mf < 4; mf++)
        aRow[mf] = (uint32_t)((warpM * 64 + mf * 16 + ((lid >> 3) & 1) * 8 + l7) * 128);
    const int aSel = lid >> 4;
    // B: p 0..3: col = warpN*64 + p*16 + (lid>>4)*8 + l7 ; c16 += (lid>>3)&1
    uint32_t bCol[4];
#pragma unroll
    for (int p = 0; p < 4; p++)
        bCol[p] = (uint32_t)((warpN * 64 + p * 16 + (lid >> 4) * 8 + l7) * 128);
    const int bSel = (lid >> 3) & 1;

    // chunk loader: 128 rows x 128B per operand, SW128 swizzle; 128 threads
    auto load_chunk = [&](const __half* __restrict__ base, int rb, int kt, uint32_t dst) {
#pragma unroll
        for (int i = 0; i < 8; i++) {
            int f = tid + i * 128;        // 0..1023 16B slots
            int r = f >> 3;
            int c16 = f & 7;
            const __half* g = base + (size_t)(rb + r) * DD + kt + c16 * 8;
            cp_async16(dst + r * 128 + ((c16 ^ (r & 7)) << 4), g);
        }
    };

    float acc[4][8][4];
#pragma unroll
    for (int mf = 0; mf < 4; mf++)
#pragma unroll
        for (int nf = 0; nf < 8; nf++)
#pragma unroll
            for (int v = 0; v < 4; v++) acc[mf][nf][v] = 0.f;

    load_chunk(g_srch, rowBase, 0, sbase + A_OFF(0));
    load_chunk(g_tgth, colBase, 0, sbase + B_OFF(0));
    asm volatile("cp.async.commit_group;");

    for (int c = 0; c < NCHUNK; c++) {
        int st = c & 1;
        if (c + 1 < NCHUNK) {
            int sn = (c + 1) & 1;
            load_chunk(g_srch, rowBase, (c + 1) * KC, sbase + A_OFF(sn));
            load_chunk(g_tgth, colBase, (c + 1) * KC, sbase + B_OFF(sn));
            asm volatile("cp.async.commit_group;");
            asm volatile("cp.async.wait_group 1;");
        } else {
            asm volatile("cp.async.wait_group 0;");
        }
        __syncthreads();

        const uint32_t Ab = sbase + A_OFF(st);
        const uint32_t Bb = sbase + B_OFF(st);
#pragma unroll
        for (int s = 0; s < 4; s++) {          // 4 x K=16
            uint32_t a[4][4];
#pragma unroll
            for (int mf = 0; mf < 4; mf++) {
                uint32_t addr = Ab + aRow[mf] + ((uint32_t)((s * 2 + aSel) ^ l7) << 4);
                ldsm_x4(addr, a[mf][0], a[mf][1], a[mf][2], a[mf][3]);
            }
#pragma unroll
            for (int p = 0; p < 4; p++) {
                uint32_t b0a, b1a, b0b, b1b;
                uint32_t addr = Bb + bCol[p] + ((uint32_t)((s * 2 + bSel) ^ l7) << 4);
                ldsm_x4(addr, b0a, b1a, b0b, b1b);
#pragma unroll
                for (int mf = 0; mf < 4; mf++) {
                    mma_f16(acc[mf][2 * p],     a[mf][0], a[mf][1], a[mf][2], a[mf][3], b0a, b1a);
                    mma_f16(acc[mf][2 * p + 1], a[mf][0], a[mf][1], a[mf][2], a[mf][3], b0b, b1b);
                }
            }
        }
        __syncthreads();
    }

    // ---- epilogue: dist -> clamp -> mask -> row max/min ----
#pragma unroll
    for (int mf = 0; mf < 4; mf++) {
#pragma unroll
        for (int half = 0; half < 2; half++) {
            int row = warpM * 64 + mf * 16 + half * 8 + gid;
            float e1v = sE1[row];
            int   lr  = sLr[row];
            float apv = 0.f;
            float anv = __int_as_float(0x7f800000);
#pragma unroll
            for (int nf = 0; nf < 8; nf++) {
                int c0 = warpN * 64 + nf * 8 + t4 * 2;
#pragma unroll
                for (int v = 0; v < 2; v++) {
                    int col = c0 + v;
                    float d = fmaf(-2.f, acc[mf][nf][half * 2 + v], e1v + sE2[col]);
                    d = fmaxf(d, 0.f);
                    if (lr == sLc[col]) apv = fmaxf(apv, d);
                    else                anv = fminf(anv, d);
                }
            }
#pragma unroll
            for (int o = 1; o <= 2; o <<= 1) {
                apv = fmaxf(apv, __shfl_xor_sync(0xffffffffu, apv, o));
                anv = fminf(anv, __shfl_xor_sync(0xffffffffu, anv, o));
            }
            if (t4 == 0) {
                atomicMax(&sAp[row], __float_as_uint(apv));
                atomicMin(&sAn[row], __float_as_uint(anv));
            }
        }
    }
    __syncthreads();
    atomicMax(&g_ap[rowBase + tid], sAp[tid]);
    atomicMin(&g_an[rowBase + tid], sAn[tid]);
}

// ---------------------------------------------------------------------------
// reduce: deterministic single-block mean; 512 threads, 8 rows/thread
// ---------------------------------------------------------------------------
__global__ void __launch_bounds__(512) reduce_kernel(float* __restrict__ out) {
    __shared__ float sw[16];
    int t = threadIdx.x;  // 512; thread t owns rows 8t..8t+7
    uint4 ap0 = *(const uint4*)&g_ap[t * 8];
    uint4 an0 = *(const uint4*)&g_an[t * 8];
    uint4 ap1 = *(const uint4*)&g_ap[t * 8 + 4];
    uint4 an1 = *(const uint4*)&g_an[t * 8 + 4];
    float s = fmaxf(__uint_as_float(ap0.x) - __uint_as_float(an0.x) + MARGIN_F, 0.f)
            + fmaxf(__uint_as_float(ap0.y) - __uint_as_float(an0.y) + MARGIN_F, 0.f)
            + fmaxf(__uint_as_float(ap0.z) - __uint_as_float(an0.z) + MARGIN_F, 0.f)
            + fmaxf(__uint_as_float(ap0.w) - __uint_as_float(an0.w) + MARGIN_F, 0.f)
            + fmaxf(__uint_as_float(ap1.x) - __uint_as_float(an1.x) + MARGIN_F, 0.f)
            + fmaxf(__uint_as_float(ap1.y) - __uint_as_float(an1.y) + MARGIN_F, 0.f)
            + fmaxf(__uint_as_float(ap1.z) - __uint_as_float(an1.z) + MARGIN_F, 0.f)
            + fmaxf(__uint_as_float(ap1.w) - __uint_as_float(an1.w) + MARGIN_F, 0.f);
#pragma unroll
    for (int o = 16; o > 0; o >>= 1) s += __shfl_xor_sync(0xffffffffu, s, o);
    if ((t & 31) == 0) sw[t >> 5] = s;
    __syncthreads();
    if (t < 16) {
        float v = sw[t];
#pragma unroll
        for (int o = 8; o > 0; o >>= 1) v += __shfl_xor_sync(0xffffu, v, o);
        if (t == 0) out[0] = v * (1.0f / (float)NN);
    }
}

// ---------------------------------------------------------------------------
extern "C" void kernel_launch(void* const* d_in, const int* in_sizes, int n_in,
                              void* d_out, int out_size) {
    const float* src = (const float*)d_in[0];
    const float* tgt = (const float*)d_in[1];
    const int*   lab = (const int*)d_in[2];

    cudaFuncSetAttribute(dist_mma_kernel,
                         cudaFuncAttributeMaxDynamicSharedMemorySize, DYN_SMEM);

    prep_kernel<<<NN / 4, 256>>>(src, tgt, lab);
    dist_mma_kernel<<<dim3(NN / BN, NN / BM), 128, DYN_SMEM>>>();
    reduce_kernel<<<1, 512>>>((float*)d_out);
}

// round 17
// speedup vs baseline: 1.2735x; 1.0396x over previous
#include <cuda_runtime.h>
#include <cuda_fp16.h>
#include <cstdint>

#define NN 4096
#define DD 512
#define BM 128
#define BN 128
#define KC 64                    // fp16 K elems per chunk = 128B per row
#define NCHUNK (DD / KC)         // 8
#define MARGIN_F 0.3f

#define TILE_BYTES (BM * 128)    // 16 KB per operand per stage
#define A_OFF(s) ((s) * TILE_BYTES)
#define B_OFF(s) (2 * TILE_BYTES + (s) * TILE_BYTES)
#define DYN_SMEM (4 * TILE_BYTES)   // 64 KB (2-stage double buffer)

__device__ float    g_e1[NN];
__device__ float    g_e2[NN];
__device__ unsigned g_ap[NN];      // non-negative float bits, atomicMax
__device__ unsigned g_an[NN];      // non-negative float bits, atomicMin
__device__ int      g_lab[NN];
__device__ __half   g_srch[NN * DD];   // fp16 copies (4 MB each)
__device__ __half   g_tgth[NN * DD];

// ---------------------------------------------------------------------------
__device__ __forceinline__ uint32_t h2_bits(__half2 h) {
    return *reinterpret_cast<uint32_t*>(&h);
}
__device__ __forceinline__ uint32_t smem_u32(const void* p) {
    uint32_t a;
    asm("{ .reg .u64 t; cvta.to.shared.u64 t, %1; cvt.u32.u64 %0, t; }"
        : "=r"(a) : "l"(p));
    return a;
}
__device__ __forceinline__ void cp_async16(uint32_t dst, const void* src) {
    asm volatile("cp.async.cg.shared.global [%0], [%1], 16;" :: "r"(dst), "l"(src));
}
__device__ __forceinline__ void ldsm_x4(uint32_t addr, uint32_t& r0, uint32_t& r1,
                                        uint32_t& r2, uint32_t& r3) {
    asm volatile("ldmatrix.sync.aligned.m8n8.x4.shared.b16 {%0,%1,%2,%3}, [%4];"
                 : "=r"(r0), "=r"(r1), "=r"(r2), "=r"(r3) : "r"(addr));
}
__device__ __forceinline__ void mma_f16(float* d, uint32_t a0, uint32_t a1,
                                        uint32_t a2, uint32_t a3,
                                        uint32_t b0, uint32_t b1) {
    asm volatile(
        "mma.sync.aligned.m16n8k16.row.col.f32.f16.f16.f32 "
        "{%0,%1,%2,%3}, {%4,%5,%6,%7}, {%8,%9}, {%0,%1,%2,%3};"
        : "+f"(d[0]), "+f"(d[1]), "+f"(d[2]), "+f"(d[3])
        : "r"(a0), "r"(a1), "r"(a2), "r"(a3), "r"(b0), "r"(b1));
}

// ---------------------------------------------------------------------------
// prep: warp-per-(row, array) fp32->fp16 convert + norms + accumulator init.
// Block 0 additionally: label dtype detect + normalize.
// (implicit PDL trigger at block completion)
// ---------------------------------------------------------------------------
__global__ void __launch_bounds__(256) prep_kernel(const float* __restrict__ src,
                                                   const float* __restrict__ tgt,
                                                   const int* __restrict__ lab32) {
    const int wid = threadIdx.x >> 5;
    const int lid = threadIdx.x & 31;
    const int slot = blockIdx.x * 8 + wid;
    const int row = slot >> 1;
    const int arr = slot & 1;

    const float* base = arr ? tgt : src;
    __half* dsth = arr ? g_tgth : g_srch;

    const float4* s4 = (const float4*)(base + (size_t)row * DD);
    uint2* oh = (uint2*)(dsth + (size_t)row * DD);

    float4 xs[4];
#pragma unroll
    for (int i = 0; i < 4; i++) xs[i] = s4[lid + 32 * i];

    float a = 0.f;
#pragma unroll
    for (int i = 0; i < 4; i++) {
        float4 x = xs[i];
        a = fmaf(x.x, x.x, a); a = fmaf(x.y, x.y, a);
        a = fmaf(x.z, x.z, a); a = fmaf(x.w, x.w, a);
        uint2 o;
        o.x = h2_bits(__floats2half2_rn(x.x, x.y));
        o.y = h2_bits(__floats2half2_rn(x.z, x.w));
        __stcg(&oh[lid + 32 * i], o);
    }
#pragma unroll
    for (int o = 16; o > 0; o >>= 1)
        a += __shfl_xor_sync(0xffffffffu, a, o);
    if (lid == 0) {
        if (arr == 0) {
            g_e1[row] = a;
            g_ap[row] = 0u;
            g_an[row] = 0x7f800000u;
        } else {
            g_e2[row] = a;
        }
    }

    if (blockIdx.x == 0) {
        __shared__ int any_odd_nonzero;
        const int t = threadIdx.x;
        if (t == 0) any_odd_nonzero = 0;
        __syncthreads();
        int local = 0;
        for (int i = 2 * t + 1; i < NN; i += 2 * 256)
            if (lab32[i] != 0) local = 1;
        if (local) atomicOr(&any_odd_nonzero, 1);
        __syncthreads();
        bool is64 = (any_odd_nonzero == 0);
        for (int i = t; i < NN; i += 256)
            g_lab[i] = is64 ? lab32[2 * i] : lab32[i];
    }
}

// ---------------------------------------------------------------------------
// dist_mma: UNCHANGED loop (128x128 CTA, 4 warps 2x2, warp tile 64x64,
// occ 2, fill-commit-wait1-sync-compute-sync). PDL secondary: waits for
// prep via cudaGridDependencySynchronize before touching its outputs.
// ---------------------------------------------------------------------------
__global__ void __launch_bounds__(128, 2) dist_mma_kernel() {
    extern __shared__ char smem[];
    __shared__ float sE1[BM], sE2[BN];
    __shared__ int   sLr[BM], sLc[BN];
    __shared__ unsigned sAp[BM], sAn[BM];

    const int tid = threadIdx.x;
    const int wid = tid >> 5;
    const int lid = tid & 31;
    const int gid = lid >> 2;
    const int t4  = lid & 3;
    const int warpM = wid & 1;    // 0..1 -> 64-row slab
    const int warpN = wid >> 1;   // 0..1 -> 64-col slab
    const int rowBase = blockIdx.y * BM;
    const int colBase = blockIdx.x * BN;

    const uint32_t sbase = smem_u32(smem);
    const int l7 = lid & 7;
    uint32_t aRow[4];
#pragma unroll
    for (int mf = 0; mf < 4; mf++)
        aRow[mf] = (uint32_t)((warpM * 64 + mf * 16 + ((lid >> 3) & 1) * 8 + l7) * 128);
    const int aSel = lid >> 4;
    uint32_t bCol[4];
#pragma unroll
    for (int p = 0; p < 4; p++)
        bCol[p] = (uint32_t)((warpN * 64 + p * 16 + (lid >> 4) * 8 + l7) * 128);
    const int bSel = (lid >> 3) & 1;

    // wait for prep grid (PDL) before reading any of its outputs
    cudaGridDependencySynchronize();

    // per-tile metadata (128 rows, 128 cols; 128 threads)
    sAp[tid] = 0u;
    sAn[tid] = 0x7f800000u;
    sE1[tid] = g_e1[rowBase + tid];
    sE2[tid] = g_e2[colBase + tid];
    sLr[tid] = g_lab[rowBase + tid];
    sLc[tid] = g_lab[colBase + tid];

    // chunk loader: 128 rows x 128B per operand, SW128 swizzle; 128 threads
    auto load_chunk = [&](const __half* __restrict__ base, int rb, int kt, uint32_t dst) {
#pragma unroll
        for (int i = 0; i < 8; i++) {
            int f = tid + i * 128;        // 0..1023 16B slots
            int r = f >> 3;
            int c16 = f & 7;
            const __half* g = base + (size_t)(rb + r) * DD + kt + c16 * 8;
            cp_async16(dst + r * 128 + ((c16 ^ (r & 7)) << 4), g);
        }
    };

    float acc[4][8][4];
#pragma unroll
    for (int mf = 0; mf < 4; mf++)
#pragma unroll
        for (int nf = 0; nf < 8; nf++)
#pragma unroll
            for (int v = 0; v < 4; v++) acc[mf][nf][v] = 0.f;

    load_chunk(g_srch, rowBase, 0, sbase + A_OFF(0));
    load_chunk(g_tgth, colBase, 0, sbase + B_OFF(0));
    asm volatile("cp.async.commit_group;");

    for (int c = 0; c < NCHUNK; c++) {
        int st = c & 1;
        if (c + 1 < NCHUNK) {
            int sn = (c + 1) & 1;
            load_chunk(g_srch, rowBase, (c + 1) * KC, sbase + A_OFF(sn));
            load_chunk(g_tgth, colBase, (c + 1) * KC, sbase + B_OFF(sn));
            asm volatile("cp.async.commit_group;");
            asm volatile("cp.async.wait_group 1;");
        } else {
            asm volatile("cp.async.wait_group 0;");
        }
        __syncthreads();

        const uint32_t Ab = sbase + A_OFF(st);
        const uint32_t Bb = sbase + B_OFF(st);
#pragma unroll
        for (int s = 0; s < 4; s++) {          // 4 x K=16
            uint32_t a[4][4];
#pragma unroll
            for (int mf = 0; mf < 4; mf++) {
                uint32_t addr = Ab + aRow[mf] + ((uint32_t)((s * 2 + aSel) ^ l7) << 4);
                ldsm_x4(addr, a[mf][0], a[mf][1], a[mf][2], a[mf][3]);
            }
#pragma unroll
            for (int p = 0; p < 4; p++) {
                uint32_t b0a, b1a, b0b, b1b;
                uint32_t addr = Bb + bCol[p] + ((uint32_t)((s * 2 + bSel) ^ l7) << 4);
                ldsm_x4(addr, b0a, b1a, b0b, b1b);
#pragma unroll
                for (int mf = 0; mf < 4; mf++) {
                    mma_f16(acc[mf][2 * p],     a[mf][0], a[mf][1], a[mf][2], a[mf][3], b0a, b1a);
                    mma_f16(acc[mf][2 * p + 1], a[mf][0], a[mf][1], a[mf][2], a[mf][3], b0b, b1b);
                }
            }
        }
        __syncthreads();
    }

    // ---- epilogue: dist -> clamp -> mask -> row max/min ----
#pragma unroll
    for (int mf = 0; mf < 4; mf++) {
#pragma unroll
        for (int half = 0; half < 2; half++) {
            int row = warpM * 64 + mf * 16 + half * 8 + gid;
            float e1v = sE1[row];
            int   lr  = sLr[row];
            float apv = 0.f;
            float anv = __int_as_float(0x7f800000);
#pragma unroll
            for (int nf = 0; nf < 8; nf++) {
                int c0 = warpN * 64 + nf * 8 + t4 * 2;
#pragma unroll
                for (int v = 0; v < 2; v++) {
                    int col = c0 + v;
                    float d = fmaf(-2.f, acc[mf][nf][half * 2 + v], e1v + sE2[col]);
                    d = fmaxf(d, 0.f);
                    if (lr == sLc[col]) apv = fmaxf(apv, d);
                    else                anv = fminf(anv, d);
                }
            }
#pragma unroll
            for (int o = 1; o <= 2; o <<= 1) {
                apv = fmaxf(apv, __shfl_xor_sync(0xffffffffu, apv, o));
                anv = fminf(anv, __shfl_xor_sync(0xffffffffu, anv, o));
            }
            if (t4 == 0) {
                atomicMax(&sAp[row], __float_as_uint(apv));
                atomicMin(&sAn[row], __float_as_uint(anv));
            }
        }
    }
    __syncthreads();
    atomicMax(&g_ap[rowBase + tid], sAp[tid]);
    atomicMin(&g_an[rowBase + tid], sAn[tid]);
}

// ---------------------------------------------------------------------------
// reduce: deterministic single-block mean; PDL secondary of dist.
// ---------------------------------------------------------------------------
__global__ void __launch_bounds__(512) reduce_kernel(float* __restrict__ out) {
    __shared__ float sw[16];
    int t = threadIdx.x;  // 512; thread t owns rows 8t..8t+7

    cudaGridDependencySynchronize();   // wait for all dist CTAs

    uint4 ap0 = *(const uint4*)&g_ap[t * 8];
    uint4 an0 = *(const uint4*)&g_an[t * 8];
    uint4 ap1 = *(const uint4*)&g_ap[t * 8 + 4];
    uint4 an1 = *(const uint4*)&g_an[t * 8 + 4];
    float s = fmaxf(__uint_as_float(ap0.x) - __uint_as_float(an0.x) + MARGIN_F, 0.f)
            + fmaxf(__uint_as_float(ap0.y) - __uint_as_float(an0.y) + MARGIN_F, 0.f)
            + fmaxf(__uint_as_float(ap0.z) - __uint_as_float(an0.z) + MARGIN_F, 0.f)
            + fmaxf(__uint_as_float(ap0.w) - __uint_as_float(an0.w) + MARGIN_F, 0.f)
            + fmaxf(__uint_as_float(ap1.x) - __uint_as_float(an1.x) + MARGIN_F, 0.f)
            + fmaxf(__uint_as_float(ap1.y) - __uint_as_float(an1.y) + MARGIN_F, 0.f)
            + fmaxf(__uint_as_float(ap1.z) - __uint_as_float(an1.z) + MARGIN_F, 0.f)
            + fmaxf(__uint_as_float(ap1.w) - __uint_as_float(an1.w) + MARGIN_F, 0.f);
#pragma unroll
    for (int o = 16; o > 0; o >>= 1) s += __shfl_xor_sync(0xffffffffu, s, o);
    if ((t & 31) == 0) sw[t >> 5] = s;
    __syncthreads();
    if (t < 16) {
        float v = sw[t];
#pragma unroll
        for (int o = 8; o > 0; o >>= 1) v += __shfl_xor_sync(0xffffu, v, o);
        if (t == 0) out[0] = v * (1.0f / (float)NN);
    }
}

// ---------------------------------------------------------------------------
extern "C" void kernel_launch(void* const* d_in, const int* in_sizes, int n_in,
                              void* d_out, int out_size) {
    const float* src = (const float*)d_in[0];
    const float* tgt = (const float*)d_in[1];
    const int*   lab = (const int*)d_in[2];

    cudaFuncSetAttribute(dist_mma_kernel,
                         cudaFuncAttributeMaxDynamicSharedMemorySize, DYN_SMEM);

    prep_kernel<<<NN / 4, 256>>>(src, tgt, lab);

    // dist: PDL secondary of prep
    {
        cudaLaunchAttribute attr[1];
        attr[0].id = cudaLaunchAttributeProgrammaticStreamSerialization;
        attr[0].val.programmaticStreamSerializationAllowed = 1;
        cudaLaunchConfig_t cfg = {};
        cfg.gridDim = dim3(NN / BN, NN / BM);
        cfg.blockDim = dim3(128, 1, 1);
        cfg.dynamicSmemBytes = DYN_SMEM;
        cfg.stream = 0;
        cfg.attrs = attr;
        cfg.numAttrs = 1;
        cudaLaunchKernelEx(&cfg, dist_mma_kernel);
    }

    // reduce: PDL secondary of dist
    {
        cudaLaunchAttribute attr[1];
        attr[0].id = cudaLaunchAttributeProgrammaticStreamSerialization;
        attr[0].val.programmaticStreamSerializationAllowed = 1;
        cudaLaunchConfig_t cfg = {};
        cfg.gridDim = dim3(1, 1, 1);
        cfg.blockDim = dim3(512, 1, 1);
        cfg.dynamicSmemBytes = 0;
        cfg.stream = 0;
        cfg.attrs = attr;
        cfg.numAttrs = 1;
        cudaLaunchKernelEx(&cfg, reduce_kernel, (float*)d_out);
    }
}